// round 4
// baseline (speedup 1.0000x reference)
#include <cuda_runtime.h>
#include <math.h>

// HouseholderRoPE: B=2,H=16,T=8192,D=64,M=8
// out = concat(q_rot, k_rot), float32, 2*B*H*T*D elements.
//
// Single fused kernel. Per block:
//   - recompute normalized Householder vectors Y and compact-WY factor W=Y*T
//     (Q = P0*P1*...*P7 = I - Y T Y^T) for its head,
//   - compute the block's 64x32 cos/sin pairs in shared (fp32 Cody-Waite
//     mod-2pi: C1=6.28125 exact * k<=1304 exact -> fp32-only accuracy ~5e-7),
//   - stream q/k rows: z - W (Y^T z), then interleaved RoPE, store.
// q/k loads are issued before the prologue so HBM streaming overlaps it.

#define BB 2
#define HH 16
#define TT 8192
#define DD 64
#define MM 8
#define EPSF 1e-8f

#define TPB 512
#define T_PER_BLOCK 64   // 16 warps * 4 t-rows per warp

__global__ void __launch_bounds__(TPB) hh_rope_fused_kernel(
    const float* __restrict__ q, const float* __restrict__ k,
    const float* __restrict__ V, const float* __restrict__ pos,
    const float* __restrict__ freq, float* __restrict__ out)
{
    __shared__ float sY[MM * DD];                 // u vectors (2KB)
    __shared__ float sW[MM * DD];                 // W = Y*T   (2KB)
    __shared__ float scs[T_PER_BLOCK * DD];       // cos/sin, 16KB (aliases sq2 early)
    __shared__ float sG[MM * MM];
    __shared__ float sT[MM * MM];
    __shared__ float rnorm[MM];
    float* sq2 = scs;                             // reuse: v*v scratch before trig

    const int nTB = TT / T_PER_BLOCK;             // 128
    const int bh  = blockIdx.x >> 7;              // 0..B*H-1
    const int tb  = blockIdx.x & (nTB - 1);
    const int h   = bh & (HH - 1);

    const int tid  = threadIdx.x;
    const int lane = tid & 31;
    const int warp = tid >> 5;
    const int j    = lane & 7;                    // d-slice within row
    const int g    = lane >> 3;                   // t row within warp

    const int t = tb * T_PER_BLOCK + warp * 4 + g;
    const size_t rowf4 = ((size_t)bh * TT + t) * (DD / 4);
    const size_t koff  = (size_t)BB * HH * TT * (DD / 4);

    const float4* q4 = (const float4*)q;
    const float4* k4 = (const float4*)k;

    // Issue streaming loads FIRST: in flight during the whole prologue.
    float4 qa = __ldcs(&q4[rowf4 + j]);
    float4 qb = __ldcs(&q4[rowf4 + 8 + j]);
    float4 ka = __ldcs(&k4[rowf4 + j]);
    float4 kb = __ldcs(&k4[rowf4 + 8 + j]);

    // ---- Prologue: Y, T, W -------------------------------------------------
    const int m = tid >> 6;                       // 0..7
    const int d = tid & 63;

    float v = __ldg(&V[h * (MM * DD) + tid]);     // (h*8+m)*64+d == h*512+tid
    sq2[tid] = v * v;
    __syncthreads();

    if (tid < MM) {
        float s = EPSF * EPSF;
        #pragma unroll 8
        for (int i = 0; i < DD; i++) s += sq2[tid * DD + i];
        rnorm[tid] = 1.0f / sqrtf(s);
    }
    __syncthreads();

    float u = v * rnorm[m];
    sY[tid] = u;
    if (tid < MM * MM) sT[tid] = (tid % 9 == 0) ? 2.0f : 0.0f;  // diag = 2
    __syncthreads();

    if (tid < 64) {                               // Gram G[i][j] = u_i . u_j
        int gi = tid >> 3, gj = tid & 7;
        float s = 0.0f;
        #pragma unroll 8
        for (int dd = 0; dd < DD; dd++) s += sY[gi * DD + dd] * sY[gj * DD + dd];
        sG[tid] = s;
    }
    __syncthreads();

    // T recurrence (lanes 0..7 of warp 0, parallel over row i, columns serial):
    //   T[i][j] = -2 * sum_{k=i..j-1} T[i][k] * G[k][j],  i<j ; diag = 2.
    if (tid < 8) {
        const int i = tid;
        #pragma unroll
        for (int j2 = 1; j2 < MM; j2++) {
            float acc = 0.0f;
            if (i < j2) {
                for (int kk = i; kk < j2; kk++) acc += sT[i * 8 + kk] * sG[kk * 8 + j2];
            }
            __syncwarp(0x000000ffu);
            if (i < j2) sT[i * 8 + j2] = -2.0f * acc;
            __syncwarp(0x000000ffu);
        }
    }

    // ---- Trig (all threads, overlaps warp-0 T recurrence) ------------------
    // fp32 Cody-Waite mod-2pi: k*6.28125 exact (8-bit * 11-bit), then C2 term.
    const int tbase = tb * T_PER_BLOCK;
    #pragma unroll
    for (int it = 0; it < 4; it++) {
        int idx = tid + TPB * it;                 // 0..2047
        int tl  = idx >> 5;
        int p   = idx & 31;
        float ang = __ldg(&pos[tbase + tl]) * __ldg(&freq[p]);  // fp32, as ref
        float kq  = rintf(ang * 0.15915494309189535f);
        float r   = fmaf(kq, -6.28125f, ang);
        r = fmaf(kq, -1.9353072e-3f, r);
        scs[tl * 64 + 2 * p]     = cosf(r);
        scs[tl * 64 + 2 * p + 1] = sinf(r);
    }
    __syncthreads();   // sT + scs complete

    // W[:,m] = sum_{k<=m} u_k * T[k][m]
    float w = 0.0f;
    #pragma unroll
    for (int kk = 0; kk <= m; kk++) w += sY[kk * DD + d] * sT[kk * 8 + m];
    sW[tid] = w;
    __syncthreads();

    // ---- Main: s = Y^T z ---------------------------------------------------
    float sq[MM], sk[MM];
    #pragma unroll
    for (int mm = 0; mm < MM; mm++) {
        float4 ya = *(const float4*)&sY[mm * DD + 4 * j];
        float4 yb = *(const float4*)&sY[mm * DD + 32 + 4 * j];
        sq[mm] = qa.x * ya.x + qa.y * ya.y + qa.z * ya.z + qa.w * ya.w
               + qb.x * yb.x + qb.y * yb.y + qb.z * yb.z + qb.w * yb.w;
        sk[mm] = ka.x * ya.x + ka.y * ya.y + ka.z * ya.z + ka.w * ya.w
               + kb.x * yb.x + kb.y * yb.y + kb.z * yb.z + kb.w * yb.w;
    }

    // Butterfly all-reduce across the 8 lanes of each row group (xor 1,2,4
    // stays in-group; all 4 row groups reduce in the same shfl instructions).
    #pragma unroll
    for (int off = 1; off < 8; off <<= 1) {
        #pragma unroll
        for (int mm = 0; mm < MM; mm++) {
            sq[mm] += __shfl_xor_sync(0xffffffffu, sq[mm], off);
            sk[mm] += __shfl_xor_sync(0xffffffffu, sk[mm], off);
        }
    }

    // z -= W s
    #pragma unroll
    for (int mm = 0; mm < MM; mm++) {
        float4 wa = *(const float4*)&sW[mm * DD + 4 * j];
        float4 wb = *(const float4*)&sW[mm * DD + 32 + 4 * j];
        qa.x -= wa.x * sq[mm]; qa.y -= wa.y * sq[mm];
        qa.z -= wa.z * sq[mm]; qa.w -= wa.w * sq[mm];
        qb.x -= wb.x * sq[mm]; qb.y -= wb.y * sq[mm];
        qb.z -= wb.z * sq[mm]; qb.w -= wb.w * sq[mm];
        ka.x -= wa.x * sk[mm]; ka.y -= wa.y * sk[mm];
        ka.z -= wa.z * sk[mm]; ka.w -= wa.w * sk[mm];
        kb.x -= wb.x * sk[mm]; kb.y -= wb.y * sk[mm];
        kb.z -= wb.z * sk[mm]; kb.w -= wb.w * sk[mm];
    }

    // RoPE from shared table: lane j's pairs are (2j,2j+1) and (16+2j,16+2j+1).
    const int tl = warp * 4 + g;
    float4 ca = *(const float4*)&scs[tl * 64 + 4 * j];
    float4 cb = *(const float4*)&scs[tl * 64 + 32 + 4 * j];

    {
        float e, o;
        e = qa.x; o = qa.y; qa.x = e * ca.x - o * ca.y; qa.y = e * ca.y + o * ca.x;
        e = qa.z; o = qa.w; qa.z = e * ca.z - o * ca.w; qa.w = e * ca.w + o * ca.z;
        e = qb.x; o = qb.y; qb.x = e * cb.x - o * cb.y; qb.y = e * cb.y + o * cb.x;
        e = qb.z; o = qb.w; qb.z = e * cb.z - o * cb.w; qb.w = e * cb.w + o * cb.z;
        e = ka.x; o = ka.y; ka.x = e * ca.x - o * ca.y; ka.y = e * ca.y + o * ca.x;
        e = ka.z; o = ka.w; ka.z = e * ca.z - o * ca.w; ka.w = e * ca.w + o * ca.z;
        e = kb.x; o = kb.y; kb.x = e * cb.x - o * cb.y; kb.y = e * cb.y + o * cb.x;
        e = kb.z; o = kb.w; kb.z = e * cb.z - o * cb.w; kb.w = e * cb.w + o * cb.z;
    }

    float4* o4 = (float4*)out;
    __stcs(&o4[rowf4 + j],            qa);
    __stcs(&o4[rowf4 + 8 + j],        qb);
    __stcs(&o4[koff + rowf4 + j],     ka);
    __stcs(&o4[koff + rowf4 + 8 + j], kb);
}

// ---------------------------------------------------------------------------
extern "C" void kernel_launch(void* const* d_in, const int* in_sizes, int n_in,
                              void* d_out, int out_size) {
    const float* q    = (const float*)d_in[0];
    const float* k    = (const float*)d_in[1];
    const float* V    = (const float*)d_in[2];
    const float* pos  = (const float*)d_in[3];
    const float* freq = (const float*)d_in[4];
    float* out = (float*)d_out;

    hh_rope_fused_kernel<<<BB * HH * (TT / T_PER_BLOCK), TPB>>>(q, k, V, pos, freq, out);
}

// round 5
// speedup vs baseline: 1.0350x; 1.0350x over previous
#include <cuda_runtime.h>
#include <math.h>

// HouseholderRoPE: B=2,H=16,T=8192,D=64,M=8
// out = concat(q_rot, k_rot), float32, 2*B*H*T*D elements.
//
// Kernel 1: cos/sin table (262144 pairs, double-precision mod-2pi) -> g_cs.
// Kernel 2: main. Per block: rebuild Y (normalized Householder vectors) and
//   W = Y*T (compact WY: P0*P1*...*P7 = I - Y T Y^T) for its head (cheap, no
//   trig), then stream 32 t-rows of q+k: z - W (Y^T z), RoPE from table.
//   Matvec math uses packed fma.rn.f32x2 (sm_100+) to halve FMA issue.

#define BB 2
#define HH 16
#define TT 8192
#define DD 64
#define MM 8
#define EPSF 1e-8f

#define TPB 256
#define T_PER_BLOCK 32   // 8 warps * 4 t-rows per warp

__device__ float g_cs[TT * DD];   // per t: 32 pairs * (cos,sin) interleaved

// ---- packed f32x2 helpers --------------------------------------------------
typedef unsigned long long ull;

__device__ __forceinline__ ull pk2(float lo, float hi) {
    ull r; asm("mov.b64 %0, {%1, %2};" : "=l"(r) : "f"(lo), "f"(hi)); return r;
}
__device__ __forceinline__ void upk2(ull v, float& lo, float& hi) {
    asm("mov.b64 {%0, %1}, %2;" : "=f"(lo), "=f"(hi) : "l"(v));
}
__device__ __forceinline__ ull fma2(ull a, ull b, ull c) {
    ull d; asm("fma.rn.f32x2 %0, %1, %2, %3;" : "=l"(d) : "l"(a), "l"(b), "l"(c));
    return d;
}
__device__ __forceinline__ ull mul2(ull a, ull b) {
    ull d; asm("mul.rn.f32x2 %0, %1, %2;" : "=l"(d) : "l"(a), "l"(b));
    return d;
}

// ---------------------------------------------------------------------------
// Kernel 1: cos/sin table. Accurate mod-2pi in double (proven: rel ~2e-7).
// ---------------------------------------------------------------------------
__global__ void setup_cs_kernel(const float* __restrict__ pos,
                                const float* __restrict__ freq) {
    int idx = blockIdx.x * blockDim.x + threadIdx.x;
    if (idx >= TT * 32) return;
    int t = idx >> 5;
    int p = idx & 31;
    float ang = pos[t] * freq[p];                 // fp32 product, as reference
    double a  = (double)ang;
    double kq = floor(a * 0.15915494309189535);   // 1/(2*pi)
    double r  = a - kq * 6.283185307179586;
    float rf  = (float)r;
    g_cs[t * 64 + 2 * p]     = cosf(rf);          // |rf|<2pi: fine under fast-math
    g_cs[t * 64 + 2 * p + 1] = sinf(rf);
}

// ---------------------------------------------------------------------------
// Kernel 2: main. 8 lanes per row, 4 rows per warp, q and k of the same t
// processed together in one thread.
// ---------------------------------------------------------------------------
__global__ void __launch_bounds__(TPB) hh_rope_kernel(
    const float* __restrict__ q, const float* __restrict__ k,
    const float* __restrict__ V, float* __restrict__ out)
{
    __shared__ float sY[MM * DD];     // 2KB
    __shared__ float sW[MM * DD];     // 2KB
    __shared__ float sv2[MM * DD];    // 2KB scratch (v*v)
    __shared__ float sG[MM * MM];
    __shared__ float sT[MM * MM];
    __shared__ float rnorm[MM];

    const int bh  = blockIdx.x >> 8;              // 0..31   (TT/32 = 256 tb)
    const int tb  = blockIdx.x & 255;
    const int h   = bh & (HH - 1);

    const int tid  = threadIdx.x;
    const int lane = tid & 31;
    const int warp = tid >> 5;
    const int j    = lane & 7;                    // d-slice within row
    const int g    = lane >> 3;                   // t row within warp

    const int t = tb * T_PER_BLOCK + warp * 4 + g;
    const size_t rowf4 = ((size_t)bh * TT + t) * (DD / 4);
    const size_t koff  = (size_t)BB * HH * TT * (DD / 4);

    const float4* q4 = (const float4*)q;
    const float4* k4 = (const float4*)k;

    // Issue all streaming loads FIRST: in flight during the whole prologue.
    float4 qa = __ldcs(&q4[rowf4 + j]);
    float4 qb = __ldcs(&q4[rowf4 + 8 + j]);
    float4 ka = __ldcs(&k4[rowf4 + j]);
    float4 kb = __ldcs(&k4[rowf4 + 8 + j]);
    const float4* cs4 = (const float4*)g_cs;      // L2-resident (re-read 32x)
    float4 ca = __ldg(&cs4[(size_t)t * 16 + j]);
    float4 cb = __ldg(&cs4[(size_t)t * 16 + 8 + j]);

    // ---- Prologue: Y, T, W (no trig) --------------------------------------
    float v0 = __ldg(&V[h * (MM * DD) + tid]);
    float v1 = __ldg(&V[h * (MM * DD) + 256 + tid]);
    sv2[tid]       = v0 * v0;
    sv2[tid + 256] = v1 * v1;
    __syncthreads();

    if (tid < MM) {
        float s = EPSF * EPSF;
        #pragma unroll 8
        for (int i = 0; i < DD; i++) s += sv2[tid * DD + i];
        rnorm[tid] = 1.0f / sqrtf(s);
    }
    __syncthreads();

    sY[tid]       = v0 * rnorm[tid >> 6];
    sY[tid + 256] = v1 * rnorm[(tid + 256) >> 6];
    if (tid < MM * MM) sT[tid] = (tid % 9 == 0) ? 2.0f : 0.0f;  // diag = 2
    __syncthreads();

    if (tid < 64) {                               // Gram G[i][j] = u_i . u_j
        int gi = tid >> 3, gj = tid & 7;
        float s = 0.0f;
        #pragma unroll 8
        for (int dd = 0; dd < DD; dd++) s += sY[gi * DD + dd] * sY[gj * DD + dd];
        sG[tid] = s;
    }
    __syncthreads();

    // T recurrence (lanes 0..7 of warp 0, parallel over row i):
    //   T[i][j] = -2 * sum_{k=i..j-1} T[i][k] * G[k][j],  i<j ; diag = 2.
    if (tid < 8) {
        const int i = tid;
        #pragma unroll
        for (int j2 = 1; j2 < MM; j2++) {
            float acc = 0.0f;
            if (i < j2) {
                for (int kk = i; kk < j2; kk++) acc += sT[i * 8 + kk] * sG[kk * 8 + j2];
            }
            __syncwarp(0x000000ffu);
            if (i < j2) sT[i * 8 + j2] = -2.0f * acc;
            __syncwarp(0x000000ffu);
        }
    }
    __syncthreads();

    // W[:,m] = sum_{k<=m} u_k * T[k][m]  (two elements per thread)
    {
        int e0 = tid, e1 = tid + 256;
        int m0 = e0 >> 6, m1 = e1 >> 6;
        int d0 = e0 & 63, d1 = e1 & 63;
        float w0 = 0.0f, w1 = 0.0f;
        for (int kk = 0; kk <= m0; kk++) w0 += sY[kk * DD + d0] * sT[kk * 8 + m0];
        for (int kk = 0; kk <= m1; kk++) w1 += sY[kk * DD + d1] * sT[kk * 8 + m1];
        sW[e0] = w0;
        sW[e1] = w1;
    }
    __syncthreads();

    // ---- Pack q/k into f32x2 pairs (register aliasing, ~free) --------------
    ull qp0 = pk2(qa.x, qa.y), qp1 = pk2(qa.z, qa.w);
    ull qp2 = pk2(qb.x, qb.y), qp3 = pk2(qb.z, qb.w);
    ull kp0 = pk2(ka.x, ka.y), kp1 = pk2(ka.z, ka.w);
    ull kp2 = pk2(kb.x, kb.y), kp3 = pk2(kb.z, kb.w);

    // ---- s = Y^T z (packed dot partials, then horizontal collapse) ---------
    float sq[MM], sk[MM];
    #pragma unroll
    for (int mm = 0; mm < MM; mm++) {
        float4 ya = *(const float4*)&sY[mm * DD + 4 * j];
        float4 yb = *(const float4*)&sY[mm * DD + 32 + 4 * j];
        ull ya01 = pk2(ya.x, ya.y), ya23 = pk2(ya.z, ya.w);
        ull yb01 = pk2(yb.x, yb.y), yb23 = pk2(yb.z, yb.w);
        ull aq = fma2(qp0, ya01, fma2(qp1, ya23, fma2(qp2, yb01, mul2(qp3, yb23))));
        ull ak = fma2(kp0, ya01, fma2(kp1, ya23, fma2(kp2, yb01, mul2(kp3, yb23))));
        float lo, hi;
        upk2(aq, lo, hi); sq[mm] = lo + hi;
        upk2(ak, lo, hi); sk[mm] = lo + hi;
    }

    // Butterfly all-reduce across the 8 lanes of each row group.
    #pragma unroll
    for (int off = 1; off < 8; off <<= 1) {
        #pragma unroll
        for (int mm = 0; mm < MM; mm++) {
            sq[mm] += __shfl_xor_sync(0xffffffffu, sq[mm], off);
            sk[mm] += __shfl_xor_sync(0xffffffffu, sk[mm], off);
        }
    }

    // ---- z -= W s (packed) -------------------------------------------------
    #pragma unroll
    for (int mm = 0; mm < MM; mm++) {
        float4 wa = *(const float4*)&sW[mm * DD + 4 * j];
        float4 wb = *(const float4*)&sW[mm * DD + 32 + 4 * j];
        ull wa01 = pk2(wa.x, wa.y), wa23 = pk2(wa.z, wa.w);
        ull wb01 = pk2(wb.x, wb.y), wb23 = pk2(wb.z, wb.w);
        float nsq = -sq[mm], nsk = -sk[mm];
        ull nq2 = pk2(nsq, nsq), nk2 = pk2(nsk, nsk);
        qp0 = fma2(wa01, nq2, qp0); qp1 = fma2(wa23, nq2, qp1);
        qp2 = fma2(wb01, nq2, qp2); qp3 = fma2(wb23, nq2, qp3);
        kp0 = fma2(wa01, nk2, kp0); kp1 = fma2(wa23, nk2, kp1);
        kp2 = fma2(wb01, nk2, kp2); kp3 = fma2(wb23, nk2, kp3);
    }

    // ---- RoPE (scalar: even' = e*c - o*s ; odd' = e*s + o*c) ---------------
    float e, o;
    upk2(qp0, e, o); qa.x = e * ca.x - o * ca.y; qa.y = e * ca.y + o * ca.x;
    upk2(qp1, e, o); qa.z = e * ca.z - o * ca.w; qa.w = e * ca.w + o * ca.z;
    upk2(qp2, e, o); qb.x = e * cb.x - o * cb.y; qb.y = e * cb.y + o * cb.x;
    upk2(qp3, e, o); qb.z = e * cb.z - o * cb.w; qb.w = e * cb.w + o * cb.z;
    upk2(kp0, e, o); ka.x = e * ca.x - o * ca.y; ka.y = e * ca.y + o * ca.x;
    upk2(kp1, e, o); ka.z = e * ca.z - o * ca.w; ka.w = e * ca.w + o * ca.z;
    upk2(kp2, e, o); kb.x = e * cb.x - o * cb.y; kb.y = e * cb.y + o * cb.x;
    upk2(kp3, e, o); kb.z = e * cb.z - o * cb.w; kb.w = e * cb.w + o * cb.z;

    float4* o4 = (float4*)out;
    __stcs(&o4[rowf4 + j],            qa);
    __stcs(&o4[rowf4 + 8 + j],        qb);
    __stcs(&o4[koff + rowf4 + j],     ka);
    __stcs(&o4[koff + rowf4 + 8 + j], kb);
}

// ---------------------------------------------------------------------------
extern "C" void kernel_launch(void* const* d_in, const int* in_sizes, int n_in,
                              void* d_out, int out_size) {
    const float* q    = (const float*)d_in[0];
    const float* k    = (const float*)d_in[1];
    const float* V    = (const float*)d_in[2];
    const float* pos  = (const float*)d_in[3];
    const float* freq = (const float*)d_in[4];
    float* out = (float*)d_out;

    setup_cs_kernel<<<(TT * 32 + 255) / 256, 256>>>(pos, freq);
    hh_rope_kernel<<<BB * HH * (TT / T_PER_BLOCK), TPB>>>(q, k, V, out);
}

// round 7
// speedup vs baseline: 2.1045x; 2.0334x over previous
#include <cuda_runtime.h>
#include <math.h>

// HouseholderRoPE: B=2,H=16,T=8192,D=64,M=8
// out = concat(q_rot, k_rot), float32, 2*B*H*T*D elements.
//
// Kernel 1 (merged setup, one launch):
//   blocks [0,1024): cos/sin table (262144 pairs, double mod-2pi) -> g_cs
//   blocks [1024,1040): per-head Y (normalized vectors) and W = Y*T
//     (compact WY: P0*..*P7 = I - Y T Y^T), warp-parallel T recurrence.
// Kernel 2 (main): thread processes q+k rows for BOTH batches at the same
//   (h,t): same Y/W and same cos/sin serve 2x the data -> L1/shared traffic
//   per row halves. Packed fma.rn.f32x2 math (bit-identical to FFMA).

#define BB 2
#define HH 16
#define TT 8192
#define DD 64
#define MM 8
#define EPSF 1e-8f

#define TPB 256
#define T_PER_BLOCK 32   // 8 warps * 4 t-rows per warp (x2 batches per thread)

__device__ float g_Y[HH * MM * DD];
__device__ float g_W[HH * MM * DD];
__device__ float g_cs[TT * DD];   // per t: 32 pairs * (cos,sin) interleaved

// ---- packed f32x2 helpers --------------------------------------------------
typedef unsigned long long ull;

__device__ __forceinline__ ull pk2(float lo, float hi) {
    ull r; asm("mov.b64 %0, {%1, %2};" : "=l"(r) : "f"(lo), "f"(hi)); return r;
}
__device__ __forceinline__ void upk2(ull v, float& lo, float& hi) {
    asm("mov.b64 {%0, %1}, %2;" : "=f"(lo), "=f"(hi) : "l"(v));
}
__device__ __forceinline__ ull fma2(ull a, ull b, ull c) {
    ull d; asm("fma.rn.f32x2 %0, %1, %2, %3;" : "=l"(d) : "l"(a), "l"(b), "l"(c));
    return d;
}
__device__ __forceinline__ ull mul2(ull a, ull b) {
    ull d; asm("mul.rn.f32x2 %0, %1, %2;" : "=l"(d) : "l"(a), "l"(b));
    return d;
}

// ---------------------------------------------------------------------------
// Merged setup kernel. 1040 blocks x 256 threads.
// ---------------------------------------------------------------------------
__global__ void setup_kernel(const float* __restrict__ V,
                             const float* __restrict__ pos,
                             const float* __restrict__ freq) {
    if (blockIdx.x < 1024) {
        // ---- cos/sin table: 256 pairs per block ----------------------------
        int idx = blockIdx.x * 256 + threadIdx.x;   // 0..262143
        int t = idx >> 5;
        int p = idx & 31;
        float ang = pos[t] * freq[p];                 // fp32 product, as ref
        double a  = (double)ang;
        double kq = floor(a * 0.15915494309189535);   // 1/(2*pi)
        double r  = a - kq * 6.283185307179586;
        float rf  = (float)r;
        g_cs[t * 64 + 2 * p]     = cosf(rf);
        g_cs[t * 64 + 2 * p + 1] = sinf(rf);
        return;
    }

    // ---- per-head Y, T, W ---------------------------------------------------
    const int hh  = blockIdx.x - 1024;            // 0..15
    const int tid = threadIdx.x;

    __shared__ float sY[MM * DD];
    __shared__ float sv2[MM * DD];
    __shared__ float sG[MM * MM];
    __shared__ float sT[MM * MM];
    __shared__ float rnorm[MM];

    float v0 = V[hh * (MM * DD) + tid];
    float v1 = V[hh * (MM * DD) + 256 + tid];
    sv2[tid]       = v0 * v0;
    sv2[tid + 256] = v1 * v1;
    __syncthreads();

    if (tid < MM) {
        float s = EPSF * EPSF;
        #pragma unroll 8
        for (int i = 0; i < DD; i++) s += sv2[tid * DD + i];
        rnorm[tid] = 1.0f / sqrtf(s);
    }
    __syncthreads();

    sY[tid]       = v0 * rnorm[tid >> 6];
    sY[tid + 256] = v1 * rnorm[(tid + 256) >> 6];
    if (tid < MM * MM) sT[tid] = (tid % 9 == 0) ? 2.0f : 0.0f;  // diag = 2
    __syncthreads();

    if (tid < 64) {                               // Gram G[i][j] = u_i . u_j
        int gi = tid >> 3, gj = tid & 7;
        float s = 0.0f;
        #pragma unroll 8
        for (int dd = 0; dd < DD; dd++) s += sY[gi * DD + dd] * sY[gj * DD + dd];
        sG[tid] = s;
    }
    __syncthreads();

    // T recurrence (lanes 0..7 of warp 0, parallel over row i):
    //   T[i][j] = -2 * sum_{k=i..j-1} T[i][k] * G[k][j],  i<j ; diag = 2.
    if (tid < 8) {
        const int i = tid;
        #pragma unroll
        for (int j2 = 1; j2 < MM; j2++) {
            float acc = 0.0f;
            if (i < j2) {
                for (int kk = i; kk < j2; kk++) acc += sT[i * 8 + kk] * sG[kk * 8 + j2];
            }
            __syncwarp(0x000000ffu);
            if (i < j2) sT[i * 8 + j2] = -2.0f * acc;
            __syncwarp(0x000000ffu);
        }
    }
    __syncthreads();

    // W[:,m] = sum_{k<=m} u_k * T[k][m]  (two elements per thread) + export Y
    {
        int e0 = tid, e1 = tid + 256;
        int m0 = e0 >> 6, m1 = e1 >> 6;
        int d0 = e0 & 63, d1 = e1 & 63;
        float w0 = 0.0f, w1 = 0.0f;
        for (int kk = 0; kk <= m0; kk++) w0 += sY[kk * DD + d0] * sT[kk * 8 + m0];
        for (int kk = 0; kk <= m1; kk++) w1 += sY[kk * DD + d1] * sT[kk * 8 + m1];
        g_W[hh * (MM * DD) + e0] = w0;
        g_W[hh * (MM * DD) + e1] = w1;
        g_Y[hh * (MM * DD) + e0] = sY[e0];
        g_Y[hh * (MM * DD) + e1] = sY[e1];
    }
}

// ---------------------------------------------------------------------------
// Main kernel. 8 lanes per row, 4 t-rows per warp; each thread handles q and k
// of BOTH batches at its (h,t) so shared Y/W reads and cs reads are amortized.
// ---------------------------------------------------------------------------
__global__ void __launch_bounds__(TPB) hh_rope_kernel(
    const float* __restrict__ q, const float* __restrict__ k,
    float* __restrict__ out)
{
    __shared__ float sY[MM * DD];
    __shared__ float sW[MM * DD];

    const int h  = blockIdx.x >> 8;               // 0..15
    const int tb = blockIdx.x & 255;

    const int tid  = threadIdx.x;
    const int lane = tid & 31;
    const int warp = tid >> 5;
    const int j    = lane & 7;                    // d-slice within row
    const int g    = lane >> 3;                   // t row within warp

    const int t = tb * T_PER_BLOCK + warp * 4 + g;
    const size_t bstr4 = (size_t)HH * TT * (DD / 4);            // batch stride
    const size_t row0  = ((size_t)h * TT + t) * (DD / 4);       // b = 0
    const size_t row1  = row0 + bstr4;                          // b = 1
    const size_t koff  = (size_t)BB * bstr4;

    const float4* q4 = (const float4*)q;
    const float4* k4 = (const float4*)k;

    // Issue all streaming loads first.
    float4 q0a = __ldcs(&q4[row0 + j]);
    float4 q0b = __ldcs(&q4[row0 + 8 + j]);
    float4 k0a = __ldcs(&k4[row0 + j]);
    float4 k0b = __ldcs(&k4[row0 + 8 + j]);
    float4 q1a = __ldcs(&q4[row1 + j]);
    float4 q1b = __ldcs(&q4[row1 + 8 + j]);
    float4 k1a = __ldcs(&k4[row1 + j]);
    float4 k1b = __ldcs(&k4[row1 + 8 + j]);
    const float4* cs4 = (const float4*)g_cs;      // L2-resident (re-read 16x)
    float4 ca = __ldg(&cs4[(size_t)t * 16 + j]);
    float4 cb = __ldg(&cs4[(size_t)t * 16 + 8 + j]);

    // Stage Y/W to shared (overlaps the in-flight q/k loads).
    sY[tid]       = __ldg(&g_Y[h * (MM * DD) + tid]);
    sY[tid + 256] = __ldg(&g_Y[h * (MM * DD) + 256 + tid]);
    sW[tid]       = __ldg(&g_W[h * (MM * DD) + tid]);
    sW[tid + 256] = __ldg(&g_W[h * (MM * DD) + 256 + tid]);
    __syncthreads();

    // Pack into f32x2 pairs.
    ull q0p0 = pk2(q0a.x, q0a.y), q0p1 = pk2(q0a.z, q0a.w);
    ull q0p2 = pk2(q0b.x, q0b.y), q0p3 = pk2(q0b.z, q0b.w);
    ull k0p0 = pk2(k0a.x, k0a.y), k0p1 = pk2(k0a.z, k0a.w);
    ull k0p2 = pk2(k0b.x, k0b.y), k0p3 = pk2(k0b.z, k0b.w);
    ull q1p0 = pk2(q1a.x, q1a.y), q1p1 = pk2(q1a.z, q1a.w);
    ull q1p2 = pk2(q1b.x, q1b.y), q1p3 = pk2(q1b.z, q1b.w);
    ull k1p0 = pk2(k1a.x, k1a.y), k1p1 = pk2(k1a.z, k1a.w);
    ull k1p2 = pk2(k1b.x, k1b.y), k1p3 = pk2(k1b.z, k1b.w);

    // s = Y^T z for all four rows; one set of Y loads serves all four.
    float s0q[MM], s0k[MM], s1q[MM], s1k[MM];
    #pragma unroll
    for (int mm = 0; mm < MM; mm++) {
        float4 ya = *(const float4*)&sY[mm * DD + 4 * j];
        float4 yb = *(const float4*)&sY[mm * DD + 32 + 4 * j];
        ull ya01 = pk2(ya.x, ya.y), ya23 = pk2(ya.z, ya.w);
        ull yb01 = pk2(yb.x, yb.y), yb23 = pk2(yb.z, yb.w);
        float lo, hi;
        ull a;
        a = fma2(q0p0, ya01, fma2(q0p1, ya23, fma2(q0p2, yb01, mul2(q0p3, yb23))));
        upk2(a, lo, hi); s0q[mm] = lo + hi;
        a = fma2(k0p0, ya01, fma2(k0p1, ya23, fma2(k0p2, yb01, mul2(k0p3, yb23))));
        upk2(a, lo, hi); s0k[mm] = lo + hi;
        a = fma2(q1p0, ya01, fma2(q1p1, ya23, fma2(q1p2, yb01, mul2(q1p3, yb23))));
        upk2(a, lo, hi); s1q[mm] = lo + hi;
        a = fma2(k1p0, ya01, fma2(k1p1, ya23, fma2(k1p2, yb01, mul2(k1p3, yb23))));
        upk2(a, lo, hi); s1k[mm] = lo + hi;
    }

    // Butterfly all-reduce across the 8 lanes of each row group.
    #pragma unroll
    for (int off = 1; off < 8; off <<= 1) {
        #pragma unroll
        for (int mm = 0; mm < MM; mm++) {
            s0q[mm] += __shfl_xor_sync(0xffffffffu, s0q[mm], off);
            s0k[mm] += __shfl_xor_sync(0xffffffffu, s0k[mm], off);
            s1q[mm] += __shfl_xor_sync(0xffffffffu, s1q[mm], off);
            s1k[mm] += __shfl_xor_sync(0xffffffffu, s1k[mm], off);
        }
    }

    // z -= W s; one set of W loads serves all four rows.
    #pragma unroll
    for (int mm = 0; mm < MM; mm++) {
        float4 wa = *(const float4*)&sW[mm * DD + 4 * j];
        float4 wb = *(const float4*)&sW[mm * DD + 32 + 4 * j];
        ull wa01 = pk2(wa.x, wa.y), wa23 = pk2(wa.z, wa.w);
        ull wb01 = pk2(wb.x, wb.y), wb23 = pk2(wb.z, wb.w);
        ull n;
        n = pk2(-s0q[mm], -s0q[mm]);
        q0p0 = fma2(wa01, n, q0p0); q0p1 = fma2(wa23, n, q0p1);
        q0p2 = fma2(wb01, n, q0p2); q0p3 = fma2(wb23, n, q0p3);
        n = pk2(-s0k[mm], -s0k[mm]);
        k0p0 = fma2(wa01, n, k0p0); k0p1 = fma2(wa23, n, k0p1);
        k0p2 = fma2(wb01, n, k0p2); k0p3 = fma2(wb23, n, k0p3);
        n = pk2(-s1q[mm], -s1q[mm]);
        q1p0 = fma2(wa01, n, q1p0); q1p1 = fma2(wa23, n, q1p1);
        q1p2 = fma2(wb01, n, q1p2); q1p3 = fma2(wb23, n, q1p3);
        n = pk2(-s1k[mm], -s1k[mm]);
        k1p0 = fma2(wa01, n, k1p0); k1p1 = fma2(wa23, n, k1p1);
        k1p2 = fma2(wb01, n, k1p2); k1p3 = fma2(wb23, n, k1p3);
    }

    // RoPE (even' = e*c - o*s ; odd' = e*s + o*c), shared ca/cb for all rows.
    float e, o;
    upk2(q0p0, e, o); q0a.x = e * ca.x - o * ca.y; q0a.y = e * ca.y + o * ca.x;
    upk2(q0p1, e, o); q0a.z = e * ca.z - o * ca.w; q0a.w = e * ca.w + o * ca.z;
    upk2(q0p2, e, o); q0b.x = e * cb.x - o * cb.y; q0b.y = e * cb.y + o * cb.x;
    upk2(q0p3, e, o); q0b.z = e * cb.z - o * cb.w; q0b.w = e * cb.w + o * cb.z;
    upk2(k0p0, e, o); k0a.x = e * ca.x - o * ca.y; k0a.y = e * ca.y + o * ca.x;
    upk2(k0p1, e, o); k0a.z = e * ca.z - o * ca.w; k0a.w = e * ca.w + o * ca.z;
    upk2(k0p2, e, o); k0b.x = e * cb.x - o * cb.y; k0b.y = e * cb.y + o * cb.x;
    upk2(k0p3, e, o); k0b.z = e * cb.z - o * cb.w; k0b.w = e * cb.w + o * cb.z;
    upk2(q1p0, e, o); q1a.x = e * ca.x - o * ca.y; q1a.y = e * ca.y + o * ca.x;
    upk2(q1p1, e, o); q1a.z = e * ca.z - o * ca.w; q1a.w = e * ca.w + o * ca.z;
    upk2(q1p2, e, o); q1b.x = e * cb.x - o * cb.y; q1b.y = e * cb.y + o * cb.x;
    upk2(q1p3, e, o); q1b.z = e * cb.z - o * cb.w; q1b.w = e * cb.w + o * cb.z;
    upk2(k1p0, e, o); k1a.x = e * ca.x - o * ca.y; k1a.y = e * ca.y + o * ca.x;
    upk2(k1p1, e, o); k1a.z = e * ca.z - o * ca.w; k1a.w = e * ca.w + o * ca.z;
    upk2(k1p2, e, o); k1b.x = e * cb.x - o * cb.y; k1b.y = e * cb.y + o * cb.x;
    upk2(k1p3, e, o); k1b.z = e * cb.z - o * cb.w; k1b.w = e * cb.w + o * cb.z;

    float4* o4 = (float4*)out;
    __stcs(&o4[row0 + j],            q0a);
    __stcs(&o4[row0 + 8 + j],        q0b);
    __stcs(&o4[koff + row0 + j],     k0a);
    __stcs(&o4[koff + row0 + 8 + j], k0b);
    __stcs(&o4[row1 + j],            q1a);
    __stcs(&o4[row1 + 8 + j],        q1b);
    __stcs(&o4[koff + row1 + j],     k1a);
    __stcs(&o4[koff + row1 + 8 + j], k1b);
}

// ---------------------------------------------------------------------------
extern "C" void kernel_launch(void* const* d_in, const int* in_sizes, int n_in,
                              void* d_out, int out_size) {
    const float* q    = (const float*)d_in[0];
    const float* k    = (const float*)d_in[1];
    const float* V    = (const float*)d_in[2];
    const float* pos  = (const float*)d_in[3];
    const float* freq = (const float*)d_in[4];
    float* out = (float*)d_out;

    setup_kernel<<<1024 + HH, 256>>>(V, pos, freq);
    hh_rope_kernel<<<HH * (TT / T_PER_BLOCK), TPB>>>(q, k, out);
}